// round 2
// baseline (speedup 1.0000x reference)
#include <cuda_runtime.h>
#include <cuda_bf16.h>

// N=131072 rows, output (N,4) f32. JAX bisection bbox relabel, BETA=1.
// One thread per (row, axis); 6 bisections of solve_o1 fused for ILP.
// Round 1 fix: accurate logf (not __logf) — selection ties (argmin/pick1)
// were flipping from fast-log noise; 60 iters to match reference trajectory.

#define NROWS 131072
#define BISECT_ITERS 60

__device__ __forceinline__ float flog(float w) {
    return logf(fmaxf(w, 1e-12f));   // accurate logf, matches _safe_log
}

__device__ __forceinline__ float smooth_l1(float x) {
    float d = fabsf(x);
    return d < 1.0f ? 0.5f * d * d : d - 0.5f;
}

__device__ __forceinline__ float eps_val(float w, float wh, float lwp) {
    return smooth_l1((w - wh) * 0.5f) + smooth_l1(flog(w) - lwp);
}

// Sign-equivalent of eps_prime: eps_prime * max(w,1e-12)  (positive scale,
// preserves all >=0 / <=0 tests; avoids a divide per eval).
__device__ __forceinline__ float eps_prime_sign(float m, float wh, float lwp) {
    float wmax = fmaxf(m, 1e-12f);
    float diff = logf(wmax) - lwp;
    float cB = fminf(fmaxf(diff, -1.0f), 1.0f);
    float cA = fminf(fmaxf((m - wh) * 0.5f, -1.0f), 1.0f);
    return fmaf(0.5f * cA, wmax, cB);
}

// sigma = w * eps_prime -> sign = sign(eps_prime_sign) flipped when w < 0.
__device__ __forceinline__ float sign_eval(float m, float wh, float lwp, bool sigma) {
    float g = eps_prime_sign(m, wh, lwp);
    if (sigma && m < 0.0f) g = -g;
    return g;
}

// Six fused bisections sharing (wh, lwp). Slots 0..2: eps_prime, 3..5: sigma.
__device__ __forceinline__ void find_min6(const float* u0, const float* v0,
                                          float wh, float lwp, float* res) {
    float u[6], v[6];
#pragma unroll
    for (int j = 0; j < 6; j++) { u[j] = u0[j]; v[j] = v0[j]; }

#pragma unroll 1
    for (int it = 0; it < BISECT_ITERS; it++) {
#pragma unroll
        for (int j = 0; j < 6; j++) {
            float m = (u[j] + v[j]) * 0.5f;
            float g = sign_eval(m, wh, lwp, j >= 3);
            bool c = (g >= 0.0f);
            v[j] = c ? m : v[j];
            u[j] = c ? u[j] : m;
        }
    }
#pragma unroll
    for (int j = 0; j < 6; j++) {
        float m  = (u[j] + v[j]) * 0.5f;
        float fu = sign_eval(u0[j], wh, lwp, j >= 3);
        float fv = sign_eval(v0[j], wh, lwp, j >= 3);
        res[j] = (fu >= 0.0f) ? u0[j] : ((fv <= 0.0f) ? v0[j] : m);
    }
}

__device__ __noinline__ float solve_o1(float wp, float wh, float a1, float b1) {
    const float EB = 2.718281828459045f;      // exp(beta) = e = np.e
    float w0  = b1 - a1;
    float lwp = flog(wp);
    float base = fmaxf(w0, fmaxf(wh - 2.0f, EB * wp));
    float disc = sqrtf(fmaxf(1.0f - 32.0f / fmaxf(wh * wh, 1e-12f), 0.0f));
    float ebwp = EB * wp;

    float u[6], v[6], c[6];
    u[0] = fmaxf(w0, wh);            v[0] = wp;                         // cA (eps')
    u[1] = fmaxf(w0, wp);            v[1] = fminf(ebwp, wh);            // c2 (eps')
    u[2] = fmaxf(base, 2.0f);        v[2] = wh;                         // c3 (eps')
    u[3] = base;                     v[3] = fminf(EB, wh);              // c4 (sigma)
    u[4] = base;                     v[4] = fminf(fminf(ebwp, wh),
                                                 wh * 0.25f * (1.0f + disc)); // c5
    u[5] = fmaxf(base, wh * 0.25f * (1.0f - disc));
                                     v[5] = fminf(ebwp, wh);            // c6
    find_min6(u, v, wh, lwp, c);

    bool small = (wh <= 5.656854249492380f);  // 4*sqrt(2)
    float ev0 = eps_val(w0,   wh, lwp);
    float ev1 = eps_val(wh,   wh, lwp);
    float ev2 = eps_val(c[1], wh, lwp);
    float ev3 = eps_val(c[2], wh, lwp);
    float ev4 = small ? eps_val(c[3], wh, lwp) : 1e30f;
    float ev5 = small ? 1e30f : eps_val(c[4], wh, lwp);
    float ev6 = small ? 1e30f : eps_val(c[5], wh, lwp);

    // first-occurrence argmin (strict <), matching jnp.argmin
    float bv = ev0, bw = w0;
    if (ev1 < bv) { bv = ev1; bw = wh;   }
    if (ev2 < bv) { bv = ev2; bw = c[1]; }
    if (ev3 < bv) { bv = ev3; bw = c[2]; }
    if (ev4 < bv) { bv = ev4; bw = c[3]; }
    if (ev5 < bv) { bv = ev5; bw = c[4]; }
    if (ev6 < bv) { bv = ev6; bw = c[5]; }

    bool branchA = fmaxf(w0, wh) < wp;
    bool branchB = fmaxf(w0, wp) < wh;
    return branchA ? c[0] : (branchB ? bw : w0);
}

__device__ __forceinline__ void solve_o2(float dp, float wp, float a2, float b2,
                                         float& dO, float& wO) {
    float wh1 = 2.0f * (dp - a2);
    float wh2 = 2.0f * (b2 - dp);
    bool trivial = wp >= fmaxf(wh1, wh2);
    float w1 = solve_o1(wp, wh1, a2, b2);
    float w2 = solve_o1(wp, wh2, a2, b2);
    float lwp = flog(wp);
    bool pick1 = eps_val(w1, wh1, lwp) <= eps_val(w2, wh2, lwp);
    float d = pick1 ? (a2 + 0.5f * w1) : (b2 + 0.5f * w2);
    float w = pick1 ? w1 : w2;
    dO = trivial ? dp : d;
    wO = trivial ? wp : w;
}

__global__ void cabb_68092411511620_kernel(
    const float* __restrict__ pred,
    const float* __restrict__ target,
    const float* __restrict__ crop,
    const float* __restrict__ prop,
    const int*   __restrict__ cases,
    float*       __restrict__ out) {
    int t = blockIdx.x * blockDim.x + threadIdx.x;
    if (t >= 2 * NROWS) return;
    int i = t >> 1;
    int a = t & 1;

    float pd = pred[i * 4 + a];
    float po = expf(pred[i * 4 + 2 + a]);
    float td = target[i * 4 + a];
    float to = expf(target[i * 4 + 2 + a]);
    float p_d = prop[i * 4 + a];
    float p_o = prop[i * 4 + 2 + a];
    float ca = 0.5f * (p_d + p_o);
    float da = p_o - p_d;
    float cropa = crop[i * 4 + a];
    int lt = cases[i * 4 + 2 * a + 0];
    int rb = cases[i * 4 + 2 * a + 1];

    // right-crop branch
    float a1r = td - 0.5f * to;
    float b1r = (cropa - ca) / da;
    float wr = solve_o1(po, 2.0f * (pd - a1r), a1r, b1r);
    float dr = a1r + 0.5f * wr;

    // left-crop branch
    float a1l = -ca / da;
    float b1l = td + 0.5f * to;
    float wl = solve_o1(po, 2.0f * (b1l - pd), a1l, b1l);
    float dl = b1l - 0.5f * wl;

    // both-crop branch (b2 == b1r since d_id == axis)
    float db, wb;
    solve_o2(pd, pd, a1l, b1r, db, wb);

    float d, w;
    if (!lt && !rb)      { d = td; w = to; }
    else if (!lt && rb)  { d = dr; w = wr; }
    else if (lt && !rb)  { d = dl; w = wl; }
    else                 { d = db; w = wb; }

    out[i * 4 + a]     = d;   // d0 or d1
    out[i * 4 + 2 + a] = w;   // w0 or w1
}

extern "C" void kernel_launch(void* const* d_in, const int* in_sizes, int n_in,
                              void* d_out, int out_size) {
    // metadata order: img, pred, target, crop_shapes, proposal_list, cases, sampling_results
    const float* pred   = (const float*)d_in[1];
    const float* target = (const float*)d_in[2];
    const float* crop   = (const float*)d_in[3];
    const float* prop   = (const float*)d_in[4];
    const int*   cases  = (const int*)d_in[5];
    float* out = (float*)d_out;

    const int total = 2 * NROWS;
    const int block = 256;
    const int grid  = (total + block - 1) / block;
    cabb_68092411511620_kernel<<<grid, block>>>(pred, target, crop, prop, cases, out);
}

// round 3
// speedup vs baseline: 4.2300x; 4.2300x over previous
#include <cuda_runtime.h>
#include <cuda_bf16.h>

// N=131072 rows, output (N,4) f32. JAX bisection bbox relabel, BETA=1.
// R3: (a) log-free bisection sign eval via exponential transform (MUFU.EX2,
//     no flat crossings -> no error amplification), selections keep exact logf;
//     (b) stream compaction by case type (none handled inline; r/l/both lists)
//     so warps are homogeneous: 4x less bisection work.

#define NROWS 131072
#define TOTAL (2 * NROWS)
#define BISECT_ITERS 44
#define E_F 2.718281828459045f
#define INV_E_F 0.36787944117144233f

__device__ int g_counts[4];
__device__ int g_tasks[3][TOTAL];

__device__ __forceinline__ float flog(float w) {
    return logf(fmaxf(w, 1e-12f));   // accurate, used only for selections
}

__device__ __forceinline__ float smooth_l1(float x) {
    float d = fabsf(x);
    return d < 1.0f ? 0.5f * d * d : d - 0.5f;
}

__device__ __forceinline__ float eps_val(float w, float wh, float lwp) {
    return smooth_l1((w - wh) * 0.5f) + smooth_l1(flog(w) - lwp);
}

// Sign-carrying eval of eps_prime (times max(w,1e-12) > 0) without log:
//   band-high (m^ >= e*wpc):  g = t + 1
//   band-low  (m^ <= wpc/e):  g = t - 1
//   middle:  sign(t + log(m^/wpc)) == sign(m^*e^t - wpc)
// where t = 0.5*clip((m-wh)/2)*m^.  Middle-band derivative is bounded below
// (>= 0.75*e^t), so MUFU.EX2 error maps to ~1e-7 relative root shift only.
// sigma = w*eps_prime: flip sign when m < 0.
__device__ __forceinline__ float bis_g(float m, float wh, float wpc,
                                       float wpc_hi, float wpc_lo, bool sigma) {
    float mh = fmaxf(m, 1e-12f);
    float cA = fminf(fmaxf((m - wh) * 0.5f, -1.0f), 1.0f);
    float t  = 0.5f * cA * mh;
    float g;
    if (mh >= wpc_hi)      g = t + 1.0f;
    else if (mh <= wpc_lo) g = t - 1.0f;
    else                   g = fmaf(mh, __expf(t), -wpc);
    if (sigma && m < 0.0f) g = -g;
    return g;
}

// Six fused bisections sharing (wh, wp). Slots 0..2: eps_prime, 3..5: sigma.
__device__ __forceinline__ void find_min6(const float* u0, const float* v0,
                                          float wh, float wpc, float* res) {
    float wpc_hi = E_F * wpc;
    float wpc_lo = INV_E_F * wpc;
    float u[6], v[6];
#pragma unroll
    for (int j = 0; j < 6; j++) { u[j] = u0[j]; v[j] = v0[j]; }

#pragma unroll 1
    for (int it = 0; it < BISECT_ITERS; it++) {
#pragma unroll
        for (int j = 0; j < 6; j++) {
            float m = (u[j] + v[j]) * 0.5f;
            bool c = bis_g(m, wh, wpc, wpc_hi, wpc_lo, j >= 3) >= 0.0f;
            v[j] = c ? m : v[j];
            u[j] = c ? u[j] : m;
        }
    }
#pragma unroll
    for (int j = 0; j < 6; j++) {
        float m  = (u[j] + v[j]) * 0.5f;
        float fu = bis_g(u0[j], wh, wpc, wpc_hi, wpc_lo, j >= 3);
        float fv = bis_g(v0[j], wh, wpc, wpc_hi, wpc_lo, j >= 3);
        res[j] = (fu >= 0.0f) ? u0[j] : ((fv <= 0.0f) ? v0[j] : m);
    }
}

__device__ __noinline__ float solve_o1(float wp, float wh, float a1, float b1) {
    float w0  = b1 - a1;
    float wpc = fmaxf(wp, 1e-12f);
    float lwp = logf(wpc);
    float base = fmaxf(w0, fmaxf(wh - 2.0f, E_F * wp));
    float disc = sqrtf(fmaxf(1.0f - 32.0f / fmaxf(wh * wh, 1e-12f), 0.0f));
    float ebwp = E_F * wp;

    float u[6], v[6], c[6];
    u[0] = fmaxf(w0, wh);            v[0] = wp;                         // cA (eps')
    u[1] = fmaxf(w0, wp);            v[1] = fminf(ebwp, wh);            // c2 (eps')
    u[2] = fmaxf(base, 2.0f);        v[2] = wh;                         // c3 (eps')
    u[3] = base;                     v[3] = fminf(E_F, wh);             // c4 (sigma)
    u[4] = base;                     v[4] = fminf(fminf(ebwp, wh),
                                                 wh * 0.25f * (1.0f + disc)); // c5
    u[5] = fmaxf(base, wh * 0.25f * (1.0f - disc));
                                     v[5] = fminf(ebwp, wh);            // c6
    find_min6(u, v, wh, wpc, c);

    bool small = (wh <= 5.656854249492380f);  // 4*sqrt(2)
    float ev0 = eps_val(w0,   wh, lwp);
    float ev1 = eps_val(wh,   wh, lwp);
    float ev2 = eps_val(c[1], wh, lwp);
    float ev3 = eps_val(c[2], wh, lwp);
    float ev4 = small ? eps_val(c[3], wh, lwp) : 1e30f;
    float ev5 = small ? 1e30f : eps_val(c[4], wh, lwp);
    float ev6 = small ? 1e30f : eps_val(c[5], wh, lwp);

    // first-occurrence argmin (strict <), matching jnp.argmin
    float bv = ev0, bw = w0;
    if (ev1 < bv) { bv = ev1; bw = wh;   }
    if (ev2 < bv) { bv = ev2; bw = c[1]; }
    if (ev3 < bv) { bv = ev3; bw = c[2]; }
    if (ev4 < bv) { bv = ev4; bw = c[3]; }
    if (ev5 < bv) { bv = ev5; bw = c[4]; }
    if (ev6 < bv) { bv = ev6; bw = c[5]; }

    bool branchA = fmaxf(w0, wh) < wp;
    bool branchB = fmaxf(w0, wp) < wh;
    return branchA ? c[0] : (branchB ? bw : w0);
}

__device__ __forceinline__ void solve_o2(float dp, float wp, float a2, float b2,
                                         float& dO, float& wO) {
    float wh1 = 2.0f * (dp - a2);
    float wh2 = 2.0f * (b2 - dp);
    bool trivial = wp >= fmaxf(wh1, wh2);
    float w1 = solve_o1(wp, wh1, a2, b2);
    float w2 = solve_o1(wp, wh2, a2, b2);
    float lwp = flog(wp);
    bool pick1 = eps_val(w1, wh1, lwp) <= eps_val(w2, wh2, lwp);
    float d = pick1 ? (a2 + 0.5f * w1) : (b2 + 0.5f * w2);
    float w = pick1 ? w1 : w2;
    dO = trivial ? dp : d;
    wO = trivial ? wp : w;
}

__global__ void k_reset() {
    g_counts[0] = 0; g_counts[1] = 0; g_counts[2] = 0; g_counts[3] = 0;
}

// Classify tasks; handle trivial 'none' case inline; build r/l/both lists.
__global__ void k_classify(const float* __restrict__ target,
                           const int*   __restrict__ cases,
                           float*       __restrict__ out) {
    int t = blockIdx.x * blockDim.x + threadIdx.x;
    if (t >= TOTAL) return;
    int i = t >> 1;
    int a = t & 1;
    int lt = cases[i * 4 + 2 * a + 0];
    int rb = cases[i * 4 + 2 * a + 1];
    int type = (lt ? 2 : 0) | (rb ? 1 : 0);   // 0=none 1=r 2=l 3=both

    if (type == 0) {
        out[i * 4 + a]     = target[i * 4 + a];
        out[i * 4 + 2 + a] = expf(target[i * 4 + 2 + a]);
    }
    int lane = threadIdx.x & 31;
#pragma unroll
    for (int ty = 1; ty <= 3; ty++) {
        unsigned m = __ballot_sync(0xffffffffu, type == ty);
        if (type == ty) {
            int leader = __ffs(m) - 1;
            int base = 0;
            if (lane == leader) base = atomicAdd(&g_counts[ty], __popc(m));
            base = __shfl_sync(m, base, leader);
            int off = __popc(m & ((1u << lane) - 1u));
            g_tasks[ty - 1][base + off] = t;
        }
    }
}

__global__ void k_solve(const float* __restrict__ pred,
                        const float* __restrict__ target,
                        const float* __restrict__ crop,
                        const float* __restrict__ prop,
                        float*       __restrict__ out) {
    int j = blockIdx.x * blockDim.x + threadIdx.x;
    int c1 = g_counts[1], c2 = g_counts[2], c3 = g_counts[3];
    int t, type;
    if (j < c1)                { type = 1; t = g_tasks[0][j]; }
    else if (j < c1 + c2)      { type = 2; t = g_tasks[1][j - c1]; }
    else if (j < c1 + c2 + c3) { type = 3; t = g_tasks[2][j - c1 - c2]; }
    else return;

    int i = t >> 1;
    int a = t & 1;
    float pd = pred[i * 4 + a];
    float po = expf(pred[i * 4 + 2 + a]);
    float td = target[i * 4 + a];
    float to = expf(target[i * 4 + 2 + a]);
    float p_d = prop[i * 4 + a];
    float p_o = prop[i * 4 + 2 + a];
    float ca = 0.5f * (p_d + p_o);
    float da = p_o - p_d;
    float cropa = crop[i * 4 + a];

    float d, w;
    if (type == 1) {                    // right-crop
        float a1r = td - 0.5f * to;
        float b1r = (cropa - ca) / da;
        w = solve_o1(po, 2.0f * (pd - a1r), a1r, b1r);
        d = a1r + 0.5f * w;
    } else if (type == 2) {             // left-crop
        float a1l = -ca / da;
        float b1l = td + 0.5f * to;
        w = solve_o1(po, 2.0f * (b1l - pd), a1l, b1l);
        d = b1l - 0.5f * w;
    } else {                            // both-crop
        float a1l = -ca / da;
        float b2  = (cropa - ca) / da;
        solve_o2(pd, pd, a1l, b2, d, w);
    }

    out[i * 4 + a]     = d;
    out[i * 4 + 2 + a] = w;
}

extern "C" void kernel_launch(void* const* d_in, const int* in_sizes, int n_in,
                              void* d_out, int out_size) {
    // metadata order: img, pred, target, crop_shapes, proposal_list, cases, sampling_results
    const float* pred   = (const float*)d_in[1];
    const float* target = (const float*)d_in[2];
    const float* crop   = (const float*)d_in[3];
    const float* prop   = (const float*)d_in[4];
    const int*   cases  = (const int*)d_in[5];
    float* out = (float*)d_out;

    const int block = 256;
    const int grid  = (TOTAL + block - 1) / block;
    k_reset<<<1, 1>>>();
    k_classify<<<grid, block>>>(target, cases, out);
    k_solve<<<grid, block>>>(pred, target, crop, prop, out);
}

// round 4
// speedup vs baseline: 10.7209x; 2.5345x over previous
#include <cuda_runtime.h>
#include <cuda_bf16.h>

// N=131072 rows, output (N,4) f32. JAX bisection bbox relabel, BETA=1.
// R4: classify kernel resolves all analytically-trivial cases inline
// (none; r/l with neither branchA nor branchB -> w=w0; both-trivial;
// both-{none,none}); only bisection-needing tasks are enqueued. Solve kernel
// runs a 5-slot fused bisection (4 branchB slots + 1 branchA slot), 34 iters.
// Counter reset via cudaMemsetAsync (no reset kernel).

#define NROWS 131072
#define TOTAL (2 * NROWS)
#define BISECT_ITERS 34
#define E_F 2.718281828459045f
#define INV_E_F 0.36787944117144233f
#define SMALL_TH 5.656854249492380f   // 4*sqrt(2)

__device__ int g_count;
__device__ int g_tasks[TOTAL];

__device__ __forceinline__ float flog(float w) {
    return logf(fmaxf(w, 1e-12f));   // accurate; selections only
}
__device__ __forceinline__ float smooth_l1(float x) {
    float d = fabsf(x);
    return d < 1.0f ? 0.5f * d * d : d - 0.5f;
}
__device__ __forceinline__ float eps_val(float w, float wh, float lwp) {
    return smooth_l1((w - wh) * 0.5f) + smooth_l1(flog(w) - lwp);
}

// Sign-carrying eval of eps_prime*max(w,1e-12) (positive scale) without log:
// outside the band [wpc/e, e*wpc] the log term is saturated (+-1); inside,
// sign(t + log(mh/wpc)) == sign(mh*e^t - wpc), one MUFU.EX2. Middle-band
// derivative bounded below -> no error amplification. sigma flips sign at m<0.
__device__ __forceinline__ float bis_g(float m, float wh, float wpc,
                                       float hi, float lo, bool sigma) {
    float mh = fmaxf(m, 1e-12f);
    float cA = fminf(fmaxf((m - wh) * 0.5f, -1.0f), 1.0f);
    float t  = 0.5f * cA * mh;
    float g;
    if (mh >= hi)      g = t + 1.0f;
    else if (mh <= lo) g = t - 1.0f;
    else               g = fmaf(mh, __expf(t), -wpc);
    if (sigma && m < 0.0f) g = -g;
    return g;
}

// ---------------- classify: resolve trivial, enqueue the rest -------------
__global__ void k_classify(const float* __restrict__ pred,
                           const float* __restrict__ target,
                           const float* __restrict__ crop,
                           const float* __restrict__ prop,
                           const int*   __restrict__ cases,
                           float*       __restrict__ out) {
    int t = blockIdx.x * blockDim.x + threadIdx.x;
    bool enq = false;
    int type = 0;
    if (t < TOTAL) {
        int i = t >> 1, a = t & 1;
        int lt = cases[i * 4 + 2 * a + 0];
        int rb = cases[i * 4 + 2 * a + 1];
        type = (lt ? 2 : 0) | (rb ? 1 : 0);   // 0=none 1=r 2=l 3=both

        if (type == 0) {
            out[i * 4 + a]     = target[i * 4 + a];
            out[i * 4 + 2 + a] = expf(target[i * 4 + 2 + a]);
        } else {
            float pd = pred[i * 4 + a];
            float td = target[i * 4 + a];
            float to = expf(target[i * 4 + 2 + a]);
            float p_d = prop[i * 4 + a];
            float p_o = prop[i * 4 + 2 + a];
            float ca = 0.5f * (p_d + p_o);
            float da = p_o - p_d;
            float cropa = crop[i * 4 + a];

            if (type != 3) {
                float po = expf(pred[i * 4 + 2 + a]);
                float a1, b1, wh;
                if (type == 1) { a1 = td - 0.5f * to; b1 = (cropa - ca) / da; wh = 2.0f * (pd - a1); }
                else           { a1 = -ca / da;       b1 = td + 0.5f * to;   wh = 2.0f * (b1 - pd); }
                float w0 = b1 - a1;
                bool bA = fmaxf(w0, wh) < po;
                bool bB = fmaxf(w0, po) < wh;
                if (!bA && !bB) {
                    float w = w0;
                    float d = (type == 1) ? (a1 + 0.5f * w) : (b1 - 0.5f * w);
                    out[i * 4 + a]     = d;
                    out[i * 4 + 2 + a] = w;
                } else enq = true;
            } else {
                float a2 = -ca / da;
                float b2 = (cropa - ca) / da;
                float wh1 = 2.0f * (pd - a2);
                float wh2 = 2.0f * (b2 - pd);
                bool trivial = pd >= fmaxf(wh1, wh2);   // wp = dp = pd here
                if (trivial) {
                    out[i * 4 + a]     = pd;
                    out[i * 4 + 2 + a] = pd;
                } else {
                    float w0 = b2 - a2;
                    bool A1 = fmaxf(w0, wh1) < pd, B1 = fmaxf(w0, pd) < wh1;
                    bool A2 = fmaxf(w0, wh2) < pd, B2 = fmaxf(w0, pd) < wh2;
                    if (!(A1 | B1 | A2 | B2)) {
                        // w1 = w2 = w0
                        float lwp = logf(fmaxf(pd, 1e-12f));
                        bool pick1 = eps_val(w0, wh1, lwp) <= eps_val(w0, wh2, lwp);
                        float d = pick1 ? (a2 + 0.5f * w0) : (b2 + 0.5f * w0);
                        out[i * 4 + a]     = d;
                        out[i * 4 + 2 + a] = w0;
                    } else enq = true;
                }
            }
        }
    }
    unsigned m = __ballot_sync(0xffffffffu, enq);
    if (enq) {
        int lane = threadIdx.x & 31;
        int leader = __ffs(m) - 1;
        int base = 0;
        if (lane == leader) base = atomicAdd(&g_count, __popc(m));
        base = __shfl_sync(m, base, leader);
        g_tasks[base + __popc(m & ((1u << lane) - 1u))] = t * 4 + type;
    }
}

// ---------------- solve: 5-slot fused bisection ---------------------------
__global__ void k_solve(const float* __restrict__ pred,
                        const float* __restrict__ target,
                        const float* __restrict__ crop,
                        const float* __restrict__ prop,
                        float*       __restrict__ out) {
    int j = blockIdx.x * blockDim.x + threadIdx.x;
    int cnt = g_count;
    if (j >= cnt) return;
    int task = g_tasks[j];
    int t = task >> 2, mode = task & 3;
    int i = t >> 1, a = t & 1;

    float pd = pred[i * 4 + a];
    float po = expf(pred[i * 4 + 2 + a]);
    float td = target[i * 4 + a];
    float to = expf(target[i * 4 + 2 + a]);
    float p_d = prop[i * 4 + a];
    float p_o = prop[i * 4 + 2 + a];
    float ca = 0.5f * (p_d + p_o);
    float da = p_o - p_d;
    float cropa = crop[i * 4 + a];

    // ---- build instance params ----
    float a1 = 0.f, b1 = 1.f;          // r/l geometry
    float a2 = 0.f, b2 = 1.f, wh1 = 1.f, wh2 = 1.f;  // both geometry
    bool hasB = false, hasA = false, B1 = false;
    float wpB = 1.f, whB = 1.f, w0B = 1.f;
    float wpA = 1.f, whA = 1.f, w0A = 1.f;

    if (mode != 3) {
        float wh;
        if (mode == 1) { a1 = td - 0.5f * to; b1 = (cropa - ca) / da; wh = 2.0f * (pd - a1); }
        else           { a1 = -ca / da;       b1 = td + 0.5f * to;   wh = 2.0f * (b1 - pd); }
        float w0 = b1 - a1;
        bool bA = fmaxf(w0, wh) < po;
        if (bA) { hasA = true; wpA = po; whA = wh; w0A = w0; }
        else    { hasB = true; wpB = po; whB = wh; w0B = w0; }   // must be branchB
    } else {
        a2 = -ca / da;
        b2 = (cropa - ca) / da;
        wh1 = 2.0f * (pd - a2);
        wh2 = 2.0f * (b2 - pd);
        float w0 = b2 - a2;
        B1 = fmaxf(w0, pd) < wh1;
        bool B2c = fmaxf(w0, pd) < wh2;
        bool A1 = fmaxf(w0, wh1) < pd;
        bool A2 = fmaxf(w0, wh2) < pd;
        // exactly one of B1/B2 for enqueued non-trivial both-tasks
        hasB = true; wpB = pd; whB = B1 ? wh1 : wh2; w0B = w0;
        bool otherA = B1 ? A2 : A1;
        if (otherA) { hasA = true; wpA = pd; whA = B1 ? wh2 : wh1; w0A = w0; }
        (void)B2c;
    }

    // ---- fill slots ----
    float u0[5], v0[5];
    float wpcB = fmaxf(wpB, 1e-12f);
    bool  smallB = (whB <= SMALL_TH);
    {
        float base = fmaxf(w0B, fmaxf(whB - 2.0f, E_F * wpB));
        float disc = sqrtf(fmaxf(1.0f - 32.0f / fmaxf(whB * whB, 1e-12f), 0.0f));
        float ebwp = E_F * wpB;
        if (hasB) {
            u0[0] = fmaxf(w0B, wpB);   v0[0] = fminf(ebwp, whB);   // c2 (eps')
            u0[1] = fmaxf(base, 2.0f); v0[1] = whB;                // c3 (eps')
            if (smallB) {
                u0[2] = base; v0[2] = fminf(E_F, whB);             // c4 (sigma)
                u0[3] = 1.0f; v0[3] = 1.0f;                        // dummy
            } else {
                u0[2] = base;                                      // c5 (sigma)
                v0[2] = fminf(fminf(ebwp, whB), whB * 0.25f * (1.0f + disc));
                u0[3] = fmaxf(base, whB * 0.25f * (1.0f - disc));  // c6 (sigma)
                v0[3] = fminf(ebwp, whB);
            }
        } else {
            u0[0] = v0[0] = u0[1] = v0[1] = u0[2] = v0[2] = u0[3] = v0[3] = 1.0f;
        }
    }
    float wpcA = fmaxf(wpA, 1e-12f);
    if (hasA) { u0[4] = fmaxf(w0A, whA); v0[4] = wpA; }            // cA (eps')
    else      { u0[4] = v0[4] = 1.0f; }

    float hiB = E_F * wpcB, loB = INV_E_F * wpcB;
    float hiA = E_F * wpcA, loA = INV_E_F * wpcA;

    // ---- fused bisection: sig pattern [e, e, s, s, e] ----
    float u[5], v[5];
#pragma unroll
    for (int s = 0; s < 5; s++) { u[s] = u0[s]; v[s] = v0[s]; }
#pragma unroll 1
    for (int it = 0; it < BISECT_ITERS; it++) {
#pragma unroll
        for (int s = 0; s < 5; s++) {
            float wh_s  = (s == 4) ? whA : whB;
            float wpc_s = (s == 4) ? wpcA : wpcB;
            float hi_s  = (s == 4) ? hiA : hiB;
            float lo_s  = (s == 4) ? loA : loB;
            bool sig    = (s == 2) | (s == 3);
            float m = (u[s] + v[s]) * 0.5f;
            bool c = bis_g(m, wh_s, wpc_s, hi_s, lo_s, sig) >= 0.0f;
            v[s] = c ? m : v[s];
            u[s] = c ? u[s] : m;
        }
    }
    float r[5];
#pragma unroll
    for (int s = 0; s < 5; s++) {
        float wh_s  = (s == 4) ? whA : whB;
        float wpc_s = (s == 4) ? wpcA : wpcB;
        float hi_s  = (s == 4) ? hiA : hiB;
        float lo_s  = (s == 4) ? loA : loB;
        bool sig    = (s == 2) | (s == 3);
        float m  = (u[s] + v[s]) * 0.5f;
        float fu = bis_g(u0[s], wh_s, wpc_s, hi_s, lo_s, sig);
        float fv = bis_g(v0[s], wh_s, wpc_s, hi_s, lo_s, sig);
        r[s] = (fu >= 0.0f) ? u0[s] : ((fv <= 0.0f) ? v0[s] : m);
    }

    // ---- branchB argmin over candidates [w0, wh, c2, c3, c4|c5, c6] ----
    float wBres = w0B;
    if (hasB) {
        float lwpB = logf(wpcB);
        float bv = eps_val(w0B, whB, lwpB), bw = w0B;
        float e1 = eps_val(whB,  whB, lwpB);
        if (e1 < bv) { bv = e1; bw = whB; }
        float e2 = eps_val(r[0], whB, lwpB);
        if (e2 < bv) { bv = e2; bw = r[0]; }
        float e3 = eps_val(r[1], whB, lwpB);
        if (e3 < bv) { bv = e3; bw = r[1]; }
        float e4 = eps_val(r[2], whB, lwpB);   // c4 if small else c5
        if (e4 < bv) { bv = e4; bw = r[2]; }
        if (!smallB) {
            float e5 = eps_val(r[3], whB, lwpB);  // c6
            if (e5 < bv) { bv = e5; bw = r[3]; }
        }
        wBres = bw;
    }

    // ---- finalize ----
    float d, w;
    if (mode != 3) {
        w = hasB ? wBres : r[4];
        d = (mode == 1) ? (a1 + 0.5f * w) : (b1 - 0.5f * w);
    } else {
        float wOther = hasA ? r[4] : w0B;
        float w1 = B1 ? wBres : wOther;
        float w2 = B1 ? wOther : wBres;
        float lwp = logf(fmaxf(pd, 1e-12f));
        bool pick1 = eps_val(w1, wh1, lwp) <= eps_val(w2, wh2, lwp);
        d = pick1 ? (a2 + 0.5f * w1) : (b2 + 0.5f * w2);
        w = pick1 ? w1 : w2;
    }
    out[i * 4 + a]     = d;
    out[i * 4 + 2 + a] = w;
}

extern "C" void kernel_launch(void* const* d_in, const int* in_sizes, int n_in,
                              void* d_out, int out_size) {
    // metadata order: img, pred, target, crop_shapes, proposal_list, cases, ...
    const float* pred   = (const float*)d_in[1];
    const float* target = (const float*)d_in[2];
    const float* crop   = (const float*)d_in[3];
    const float* prop   = (const float*)d_in[4];
    const int*   cases  = (const int*)d_in[5];
    float* out = (float*)d_out;

    void* cnt_ptr = nullptr;
    cudaGetSymbolAddress(&cnt_ptr, g_count);
    cudaMemsetAsync(cnt_ptr, 0, sizeof(int));

    const int block = 256;
    const int grid  = (TOTAL + block - 1) / block;
    k_classify<<<grid, block>>>(pred, target, crop, prop, cases, out);
    k_solve<<<grid, block>>>(pred, target, crop, prop, out);
}